// round 12
// baseline (speedup 1.0000x reference)
#include <cuda_runtime.h>

// ---------------------------------------------------------------------------
// TSDCD fused kernel, GB300 / sm_103a — 512-thread, BF=4, j-unroll-2 main
//
//   E[j,k] = exp(-mask_param[j,k]);  adj = u / (E + u*(1-E))  (== sigmoid(mp+logit(u)))
//   fixed mask: column k>=64 keeps all j except j==k; column k<64 keeps only j==k
//   s[b,k,j] = adj[b,j,k] * all_var[b,j];  all_var = cat(z, x)
//   h = s@W0[k]+b0; leaky(.01); @W1[k]+b1; leaky; .W2[k]+b2 -> mu[b,k]
//   logp = -0.5*((av-mu)/std)^2 - 0.5*logvar - 0.5*log(2pi); recons = mean_b sum_k
// out: [0]=recons, [1..1+B*D)=mu row-major, [1+B*D..+D)=std
// ---------------------------------------------------------------------------

#define DTOT 320
#define DZ   64
#define DX   256
#define BATCH 1024
#define NEG  0.01f
#define HLOG2PI 0.91893853320467274178f
#define BF 4
#define NTHR 512

// shared layout (float offsets)
#define W0_STRIDE 5124          // 320*16+4 : mod32=4 -> conflict-free, 16B aligned
#define W1_STRIDE 260
#define AV_STRIDE 36            // 32+4 : float4-aligned, mod32=4
#define SM_W0 0                                  // 8*5124 = 40992
#define SM_W1 (SM_W0 + 8*W0_STRIDE)              // 2080
#define SM_AV (SM_W1 + 8*W1_STRIDE)              // 256*36 = 9216
#define SM_E  (SM_AV + 256*AV_STRIDE)            // 2560 floats (E only)
#define SM_B0 (SM_E + 2560)
#define SM_B1 (SM_B0 + 128)
#define SM_W2 (SM_B1 + 128)
#define SM_B2 (SM_W2 + 128)
#define SM_TOTAL (SM_B2 + 8)                     // 55240 floats = 220960 B
#define SMEM_BYTES (SM_TOTAL * 4)
#define SM_RED SM_AV                             // red aliases av (guarded by sync)

__device__ float g_partials[384];   // 0..127 main CTAs, 128..383 latent blocks

typedef unsigned long long ull;

static __device__ __forceinline__ ull pack2(float lo, float hi) {
    ull r; asm("mov.b64 %0, {%1, %2};" : "=l"(r) : "f"(lo), "f"(hi)); return r;
}
static __device__ __forceinline__ void unpack2(ull v, float& lo, float& hi) {
    asm("mov.b64 {%0, %1}, %2;" : "=f"(lo), "=f"(hi) : "l"(v));
}
static __device__ __forceinline__ ull ffma2(ull a, ull b, ull c) {
    ull d; asm("fma.rn.f32x2 %0, %1, %2, %3;" : "=l"(d) : "l"(a), "l"(b), "l"(c));
    return d;
}

// ---------------------------------------------------------------------------
// main kernel: observed k in [64,320)
// grid (32 kg, 4 bsplit) = 128 CTAs, 512 threads, ~221KB dyn smem
// lanes: k8 = tid&7, blane = tid>>3 (0..63); BF=4 batches/thread (b+64*o)
// one pass covers all 256 batches of the bsplit; 10 chunks of 32 j
// ---------------------------------------------------------------------------
__global__ void __launch_bounds__(NTHR, 1)
main_kernel(const float* __restrict__ x, const float* __restrict__ z,
            const float* __restrict__ u, const float* __restrict__ mp,
            const float* __restrict__ W0, const float* __restrict__ b0,
            const float* __restrict__ W1, const float* __restrict__ b1,
            const float* __restrict__ W2, const float* __restrict__ b2,
            const float* __restrict__ logvar,
            float* __restrict__ out) {
    extern __shared__ float smem[];
    float*  W0s = smem + SM_W0;
    float*  W1s = smem + SM_W1;
    float*  avs = smem + SM_AV;
    float*  Es  = smem + SM_E;
    float*  b0s = smem + SM_B0;
    float*  b1s = smem + SM_B1;
    float*  W2s = smem + SM_W2;
    float*  b2s = smem + SM_B2;
    float*  red = smem + SM_RED;

    const int tid    = threadIdx.x;
    const int kg     = blockIdx.x;
    const int bsplit = blockIdx.y;
    const int kbase  = DZ + kg * 8;
    const int k8     = tid & 7;
    const int blane  = tid >> 3;             // 0..63
    const int kglob  = kbase + k8;
    const int bbase  = bsplit * 256;

    // ---- CTA-resident tables ----
    for (int i = tid; i < 8 * 1280; i += NTHR) {          // W0 slice, float4
        int kk = i / 1280, r = i % 1280;
        ((float4*)(W0s + kk * W0_STRIDE))[r] =
            ((const float4*)(W0 + (size_t)(kbase + kk) * 5120))[r];
    }
    for (int i = tid; i < 8 * 64; i += NTHR) {            // W1 slice, float4
        int kk = i / 64, r = i % 64;
        ((float4*)(W1s + kk * W1_STRIDE))[r] =
            ((const float4*)(W1 + (size_t)(kbase + kk) * 256))[r];
    }
    for (int i = tid; i < 2560; i += NTHR) {              // E table from mask_param
        int j = i >> 3, kk = i & 7;
        Es[i] = __expf(-__ldg(mp + (size_t)j * DTOT + kbase + kk));
    }
    if (tid < 128) {
        b0s[tid] = b0[kbase * 16 + tid];
        b1s[tid] = b1[kbase * 16 + tid];
        W2s[tid] = W2[kbase * 16 + tid];
    }
    if (tid < 8) b2s[tid] = b2[kbase + tid];
    __syncthreads();

    const float lv   = __ldg(logvar + kglob);
    const float istd = __expf(-0.5f * lv);
    const float lpc  = -0.5f * lv - HLOG2PI;
    float lpsum = 0.0f;

    const float* W0k = W0s + k8 * W0_STRIDE;

    const float* up[BF];
#pragma unroll
    for (int o = 0; o < BF; o++)
        up[o] = u + (size_t)(bbase + blane + 64 * o) * (DTOT * DTOT) + kglob;

    ull acc[BF][8];
#pragma unroll
    for (int o = 0; o < BF; o++)
#pragma unroll
        for (int q = 0; q < 8; q++)
            acc[o][q] = pack2(b0s[k8 * 16 + 2 * q], b0s[k8 * 16 + 2 * q + 1]);

    float uc0[BF], uc1[BF];
#pragma unroll
    for (int o = 0; o < BF; o++) {
        uc0[o] = __ldg(up[o]);
        uc1[o] = __ldg(up[o] + DTOT);
    }

#pragma unroll 1
    for (int chunk = 0; chunk < 10; chunk++) {
        const int cb = chunk * 32;
        __syncthreads();                 // previous chunk consumers done
        // fill av tile [256 b][32 j] as float4
        for (int q = tid; q < 2048; q += NTHR) {
            int r = q >> 3, c4 = (q & 7) * 4;
            int jg = cb + c4;
            const float* src = (jg < DZ)
                ? (z + (size_t)(bbase + r) * DZ + jg)
                : (x + (size_t)(bbase + r) * DX + (jg - DZ));
            *(float4*)(avs + r * AV_STRIDE + c4) = *(const float4*)src;
        }
        __syncthreads();                 // av tile ready

#pragma unroll 1
        for (int jj = 0; jj < 32; jj += 2) {
            int jn0 = cb + jj + 2; if (jn0 > 319) jn0 = 319;   // tail dummy
            int jn1 = cb + jj + 3; if (jn1 > 319) jn1 = 319;
            float un0[BF], un1[BF];
#pragma unroll
            for (int o = 0; o < BF; o++) {
                un0[o] = __ldg(up[o] + (size_t)jn0 * DTOT);
                un1[o] = __ldg(up[o] + (size_t)jn1 * DTOT);
            }
            float2 av2[BF];
#pragma unroll
            for (int o = 0; o < BF; o++)
                av2[o] = *(const float2*)(avs + (blane + 64 * o) * AV_STRIDE + jj);

            // ---- j0 ----
            {
                const int jg = cb + jj;
                const float E = Es[jg * 8 + k8];
                const float A = 1.0f - E;
                const ulonglong2* wrp = (const ulonglong2*)(W0k + jg * 16);
                ull ss[BF];
#pragma unroll
                for (int o = 0; o < BF; o++) {
                    float uu = uc0[o];
                    float s  = __fdividef(uu * av2[o].x, fmaf(uu, A, E));
                    ss[o] = pack2(s, s);
                }
#pragma unroll
                for (int q = 0; q < 4; q++) {
                    ulonglong2 w = wrp[q];
#pragma unroll
                    for (int o = 0; o < BF; o++) {
                        acc[o][2 * q]     = ffma2(ss[o], w.x, acc[o][2 * q]);
                        acc[o][2 * q + 1] = ffma2(ss[o], w.y, acc[o][2 * q + 1]);
                    }
                }
            }
            // ---- j1 ----
            {
                const int jg = cb + jj + 1;
                const float E = Es[jg * 8 + k8];
                const float A = 1.0f - E;
                const ulonglong2* wrp = (const ulonglong2*)(W0k + jg * 16);
                ull ss[BF];
#pragma unroll
                for (int o = 0; o < BF; o++) {
                    float uu = uc1[o];
                    float s  = __fdividef(uu * av2[o].y, fmaf(uu, A, E));
                    ss[o] = pack2(s, s);
                }
#pragma unroll
                for (int q = 0; q < 4; q++) {
                    ulonglong2 w = wrp[q];
#pragma unroll
                    for (int o = 0; o < BF; o++) {
                        acc[o][2 * q]     = ffma2(ss[o], w.x, acc[o][2 * q]);
                        acc[o][2 * q + 1] = ffma2(ss[o], w.y, acc[o][2 * q + 1]);
                    }
                }
            }
#pragma unroll
            for (int o = 0; o < BF; o++) { uc0[o] = un0[o]; uc1[o] = un1[o]; }
        }
    }

    // ---- epilogue per batch: diag correction, layers 1/2, logp ----
#pragma unroll 1
    for (int o = 0; o < BF; o++) {
        const int b = bbase + blane + 64 * o;
        float u_kk  = __ldg(u + (size_t)b * (DTOT * DTOT) + (size_t)kglob * DTOT + kglob);
        float av_kk = __ldg(x + (size_t)b * DX + (kglob - DZ));
        float Ekk   = Es[kglob * 8 + k8];
        float skk   = __fdividef(u_kk * av_kk, fmaf(u_kk, 1.0f - Ekk, Ekk));
        const float* w0kk = W0k + kglob * 16;

        float hv[16];
#pragma unroll
        for (int q = 0; q < 8; q++) {
            float lo, hi;
            unpack2(acc[o][q], lo, hi);
            float c0 = fmaf(-skk, w0kk[2 * q],     lo);
            float c1 = fmaf(-skk, w0kk[2 * q + 1], hi);
            hv[2 * q]     = fmaxf(c0, NEG * c0);
            hv[2 * q + 1] = fmaxf(c1, NEG * c1);
        }
        float gv[16];
#pragma unroll
        for (int gg = 0; gg < 16; gg++) gv[gg] = b1s[k8 * 16 + gg];
#pragma unroll
        for (int hh = 0; hh < 16; hh++) {
            float hvv = hv[hh];
            const float4* w1r = (const float4*)(W1s + k8 * W1_STRIDE + hh * 16);
#pragma unroll
            for (int q = 0; q < 4; q++) {
                float4 w = w1r[q];
                gv[4 * q + 0] = fmaf(hvv, w.x, gv[4 * q + 0]);
                gv[4 * q + 1] = fmaf(hvv, w.y, gv[4 * q + 1]);
                gv[4 * q + 2] = fmaf(hvv, w.z, gv[4 * q + 2]);
                gv[4 * q + 3] = fmaf(hvv, w.w, gv[4 * q + 3]);
            }
        }
        float mu = b2s[k8];
#pragma unroll
        for (int gg = 0; gg < 16; gg++) {
            float gl = fmaxf(gv[gg], NEG * gv[gg]);
            mu = fmaf(gl, W2s[k8 * 16 + gg], mu);
        }
        out[1 + (size_t)b * DTOT + kglob] = mu;

        float d = (av_kk - mu) * istd;
        lpsum += fmaf(-0.5f * d, d, lpc);
    }

    // ---- deterministic CTA reduction (red aliases av region) ----
    __syncthreads();                 // all av reads complete before aliasing
    red[tid] = lpsum;
    __syncthreads();
    for (int sft = 256; sft > 0; sft >>= 1) {
        if (tid < sft) red[tid] += red[tid + sft];
        __syncthreads();
    }
    if (tid == 0) g_partials[bsplit * 32 + kg] = red[0];
}

// ---------------------------------------------------------------------------
// latent kernel: k in [0,64) -> only j==k contributes
// ---------------------------------------------------------------------------
__global__ void __launch_bounds__(256)
latent_kernel(const float* __restrict__ z, const float* __restrict__ u,
              const float* __restrict__ mp,
              const float* __restrict__ W0, const float* __restrict__ b0,
              const float* __restrict__ W1, const float* __restrict__ b1,
              const float* __restrict__ W2, const float* __restrict__ b2,
              const float* __restrict__ logvar,
              float* __restrict__ out) {
    __shared__ float W1s[256], W0r[16], b0r[16], b1r[16], W2r[16];
    __shared__ float red[256];

    const int tid = threadIdx.x;
    const int k   = blockIdx.x;
    const int bq  = blockIdx.y;
    const int b   = bq * 256 + tid;

    if (tid < 16) {
        W0r[tid] = __ldg(W0 + ((size_t)k * DTOT + k) * 16 + tid);
        b0r[tid] = __ldg(b0 + k * 16 + tid);
        b1r[tid] = __ldg(b1 + k * 16 + tid);
        W2r[tid] = __ldg(W2 + k * 16 + tid);
    }
    W1s[tid] = __ldg(W1 + (size_t)k * 256 + tid);
    __syncthreads();

    float E  = __expf(-__ldg(mp + (size_t)k * DTOT + k));
    float uu = __ldg(u + (size_t)b * (DTOT * DTOT) + (size_t)k * DTOT + k);
    float zv = __ldg(z + (size_t)b * DZ + k);
    float adj = __fdividef(uu, fmaf(uu, 1.0f - E, E));
    float val = adj * zv;

    float hv[16];
#pragma unroll
    for (int i = 0; i < 16; i++) {
        float c = fmaf(val, W0r[i], b0r[i]);
        hv[i] = fmaxf(c, NEG * c);
    }
    float gv[16];
#pragma unroll
    for (int gg = 0; gg < 16; gg++) gv[gg] = b1r[gg];
#pragma unroll
    for (int hh = 0; hh < 16; hh++) {
        float hvv = hv[hh];
#pragma unroll
        for (int gg = 0; gg < 16; gg++)
            gv[gg] = fmaf(hvv, W1s[hh * 16 + gg], gv[gg]);
    }
    float mu = __ldg(b2 + k);
#pragma unroll
    for (int gg = 0; gg < 16; gg++) {
        float gl = fmaxf(gv[gg], NEG * gv[gg]);
        mu = fmaf(gl, W2r[gg], mu);
    }
    out[1 + (size_t)b * DTOT + k] = mu;

    float lv = __ldg(logvar + k);
    float istd = __expf(-0.5f * lv);
    float d = (zv - mu) * istd;
    red[tid] = fmaf(-0.5f * d, d, -0.5f * lv - HLOG2PI);
    __syncthreads();
    for (int sft = 128; sft > 0; sft >>= 1) {
        if (tid < sft) red[tid] += red[tid + sft];
        __syncthreads();
    }
    if (tid == 0) g_partials[128 + k * 4 + bq] = red[0];
}

// ---------------------------------------------------------------------------
// final: 384-thread deterministic reduction + std output
// ---------------------------------------------------------------------------
__global__ void final_kernel(const float* __restrict__ logvar,
                             float* __restrict__ out) {
    __shared__ float red[384];
    const int tid = threadIdx.x;
    red[tid] = g_partials[tid];
    __syncthreads();
    if (tid < 128) red[tid] += red[tid + 256];
    __syncthreads();
    for (int sft = 128; sft > 0; sft >>= 1) {
        if (tid < sft) red[tid] += red[tid + sft];
        __syncthreads();
    }
    if (tid == 0) out[0] = red[0] * (1.0f / 1024.0f);
    if (tid < DTOT) out[1 + BATCH * DTOT + tid] = expf(0.5f * __ldg(logvar + tid));
}

// ---------------------------------------------------------------------------
extern "C" void kernel_launch(void* const* d_in, const int* in_sizes, int n_in,
                              void* d_out, int out_size) {
    const float* x      = (const float*)d_in[0];
    const float* z      = (const float*)d_in[1];
    const float* u      = (const float*)d_in[2];
    const float* mp     = (const float*)d_in[3];
    const float* W0     = (const float*)d_in[4];
    const float* b0     = (const float*)d_in[5];
    const float* W1     = (const float*)d_in[6];
    const float* b1     = (const float*)d_in[7];
    const float* W2     = (const float*)d_in[8];
    const float* b2     = (const float*)d_in[9];
    const float* logvar = (const float*)d_in[10];
    float* out = (float*)d_out;

    cudaFuncSetAttribute(main_kernel, cudaFuncAttributeMaxDynamicSharedMemorySize,
                         SMEM_BYTES);

    main_kernel<<<dim3(32, 4), NTHR, SMEM_BYTES>>>(x, z, u, mp, W0, b0, W1, b1,
                                                   W2, b2, logvar, out);
    latent_kernel<<<dim3(64, 4), 256>>>(z, u, mp, W0, b0, W1, b1, W2, b2, logvar, out);
    final_kernel<<<1, 384>>>(logvar, out);
}